// round 15
// baseline (speedup 1.0000x reference)
#include <cuda_runtime.h>
#include <cstdint>

// Problem constants (fixed by the dataset)
#define BATCH   16
#define C_IN    64
#define HH      32
#define WW      32
#define C_OUT   128
#define PW      40          // padded row: 4 left + 32 + 4 right (leaf col = x+kj+3 <= 36)
#define PLANE   (34*PW)     // 1360 floats (rows 0..33; interior rows 1..32)
#define PLANE4  (PLANE/4)   // 340

// 16B async copy global->shared (LDGSTS.128)
__device__ __forceinline__ void cp16(float* dst_smem, const float* src) {
    uint32_t d = (uint32_t)__cvta_generic_to_shared(dst_smem);
    asm volatile("cp.async.cg.shared.global [%0], [%1], 16;\n" :: "r"(d), "l"(src));
}

// gate(a,b) = c0 + ca*a + cb*b + cab*a*b, factored to 3 FMAs
__device__ __forceinline__ float gate3(const float4 k, float a, float b) {
    return fmaf(fmaf(k.w, b, k.y), a, fmaf(k.z, b, k.x));
}

// ---------------------------------------------------------------------------
// 128-thread block per (batch, oc); grid 2048. 32 regs x 128 thr x 16 blocks
// = one SM's regfile -> 16 blocks/SM cap -> the whole grid in ONE wave
// (~14 blocks, ~55 warps per SM). Small blocks de-phase memory bursts; the
// single barrier covers only 4 warps. PW=40 with zeroed side pads makes every
// leaf read (rows 0..33, cols 3..36) in-bounds and exactly zero outside the
// image. Hot loop: 8 LDS + 21 FMA + 1 STG per pixel, 8 px/thread.
// ---------------------------------------------------------------------------
__global__ void __launch_bounds__(128, 16)
tree_kernel(const float* __restrict__ x,
            const float* __restrict__ w,
            const int*   __restrict__ leaf_idx,
            float*       __restrict__ out)
{
    __shared__ __align__(16) float  sm[2 * PLANE];   // 10880 B
    __shared__ __align__(16) float  s_coef[16];
    __shared__ int s_off[8];

    const int blk = blockIdx.x;          // 0..2047
    const int oc  = blk & (C_OUT - 1);
    const int b   = blk >> 7;
    const int tid = threadIdx.x;         // 0..127

    // --- channels (broadcast LDG; const-div -> mul-hi) ---------------------
    const int chA = __ldg(&leaf_idx[oc * 8 + 0]) / 9;
    const int chB = __ldg(&leaf_idx[oc * 8 + 4]) / 9;

    // --- leaf offsets: threads 0..7 ----------------------------------------
    if (tid < 8) {
        int idx = __ldg(&leaf_idx[oc * 8 + tid]);
        int ch  = idx / 9;
        int pos = idx - ch * 9;
        int ki  = pos / 3;
        int kj  = pos - ki * 3;
        s_off[tid] = (tid >> 2) * PLANE + ki * PW + kj + 3;
    }

    // --- softmax -> 4 affine coefficients, threads 0..3 (gate = tid) -------
    // op order: 0, ab, a-ab, a, b-ab, b, s-2ab, s-ab, 1-(s-ab), 1-(s-2ab),
    //           1-b, 1-b+ab, 1-a, 1-a+ab, 1-ab, 1
    if (tid < 4) {
        const float T0[16]  = {0,0,0,0,0,0,0,0, 1, 1, 1, 1, 1, 1, 1, 1};
        const float TA[16]  = {0,0,1,1,0,0,1,1,-1,-1, 0, 0,-1,-1, 0, 0};
        const float TB[16]  = {0,0,0,0,1,1,1,1,-1,-1,-1,-1, 0, 0, 0, 0};
        const float TAB[16] = {0,1,-1,0,-1,0,-2,-1, 1, 2, 0, 1, 0, 1,-1, 0};

        const float* wp = w + (oc * 7 + tid) * 16;   // weights [C_out, 7, 16]

        float m = wp[0];
        #pragma unroll
        for (int i = 1; i < 16; i++) m = fmaxf(m, wp[i]);

        float e[16];
        float s = 0.f;
        #pragma unroll
        for (int i = 0; i < 16; i++) { e[i] = __expf(wp[i] - m); s += e[i]; }
        float inv = 1.f / s;

        float c0 = 0.f, ca = 0.f, cb = 0.f, cab = 0.f;
        #pragma unroll
        for (int i = 0; i < 16; i++) {
            c0  += e[i] * T0[i];
            ca  += e[i] * TA[i];
            cb  += e[i] * TB[i];
            cab += e[i] * TAB[i];
        }
        s_coef[tid * 4 + 0] = c0 * inv;
        s_coef[tid * 4 + 1] = ca * inv;
        s_coef[tid * 4 + 2] = cb * inv;
        s_coef[tid * 4 + 3] = cab * inv;
    }

    // --- zero borders (84 float4 per plane, slots padded to 128) -----------
    // k<68: col-groups {0,9} (cols 0-3, 36-39) of rows 0..33;
    // 68..75: row 0 groups 1..8; 76..83: row 33 groups 1..8.
    {
        float4 z = make_float4(0.f, 0.f, 0.f, 0.f);
        #pragma unroll
        for (int i = 0; i < 2; i++) {
            int t = tid + i * 128;       // 0..255 = 2 planes x 128 slots
            int p = t >> 7;              // plane 0/1
            int k = t & 127;
            if (k < 84) {
                int f4;
                if (k < 68)      f4 = (k >> 1) * 10 + ((k & 1) ? 9 : 0);
                else if (k < 76) f4 = k - 67;            // row 0, groups 1..8
                else             f4 = 330 + (k - 75);    // row 33, groups 1..8
                ((float4*)sm)[p * PLANE4 + f4] = z;
            }
        }
    }

    // --- stage: 2 planes x 32 rows x 8 chunks = 512 cp16 (4 per thread) ----
    {
        const float* xb = x + ((size_t)b * C_IN) * (HH * WW);
        #pragma unroll
        for (int i = 0; i < 4; i++) {
            int t  = tid + i * 128;      // 0..511
            int p  = t >> 8;
            int j  = t & 255;            // r*8 + c4
            int r  = j >> 3;
            int c4 = j & 7;
            const float* src = xb + ((p ? chB : chA) << 10) + j * 4;
            cp16(sm + p * PLANE + (r + 1) * PW + 4 + c4 * 4, src);
        }
        asm volatile("cp.async.commit_group;\n");
    }

    asm volatile("cp.async.wait_group 0;\n");
    __syncthreads();                     // 4 warps only

    // Coefficients to registers (4x LDS.128)
    const float4* cf = (const float4*)s_coef;
    const float4 k0 = cf[0], k1 = cf[1], k2 = cf[2], k3 = cf[3];

    // Per-thread base pixel: y0 = tid>>5 (0..3), x = tid&31; rows y0+4t
    const int pb0 = (tid >> 5) * PW + (tid & 31);
    const int o0 = s_off[0] + pb0, o1 = s_off[1] + pb0;
    const int o2 = s_off[2] + pb0, o3 = s_off[3] + pb0;
    const int o4 = s_off[4] + pb0, o5 = s_off[5] + pb0;
    const int o6 = s_off[6] + pb0, o7 = s_off[7] + pb0;

    float* ob = out + (size_t)blk * (HH * WW) + tid;

    #pragma unroll
    for (int t = 0; t < 8; t++) {
        const int d = t * 4 * PW;        // +4 rows per step (128 pixels)

        float l0 = sm[o0 + d], l1 = sm[o1 + d];
        float l2 = sm[o2 + d], l3 = sm[o3 + d];
        float l4 = sm[o4 + d], l5 = sm[o5 + d];
        float l6 = sm[o6 + d], l7 = sm[o7 + d];

        // level 0: weight rows 0,1,2,3
        float m0 = gate3(k0, l0, l1);
        float m1 = gate3(k1, l2, l3);
        float m2 = gate3(k2, l4, l5);
        float m3 = gate3(k3, l6, l7);
        // level 1: rows 1,2
        float n0 = gate3(k1, m0, m1);
        float n1 = gate3(k2, m2, m3);
        // level 2: row 3
        float r  = gate3(k3, n0, n1);

        ob[t * 128] = r;
    }
}

extern "C" void kernel_launch(void* const* d_in, const int* in_sizes, int n_in,
                              void* d_out, int out_size)
{
    const float* x   = (const float*)d_in[0];          // [16,64,32,32]
    const float* w   = (const float*)d_in[1];          // [128,7,16]
    const int*   idx = (const int*)d_in[2];            // [128,8]
    float*       out = (float*)d_out;                  // [16,128,32,32]

    tree_kernel<<<BATCH * C_OUT, 128>>>(x, w, idx, out);
}

// round 16
// speedup vs baseline: 1.2316x; 1.2316x over previous
#include <cuda_runtime.h>
#include <cstdint>

// Problem constants (fixed by the dataset)
#define BATCH   16
#define C_IN    64
#define HH      32
#define WW      32
#define C_OUT   128
#define PW      36          // padded row: 4 left + 32 data (cols 4..35)
#define PLANE   (34*PW)     // 1224 floats (rows 0..33; interior rows 1..32)
#define PLANE4  (PLANE/4)   // 306
// Leaf reads span cols 3..36. Col 36 wraps to (row+1, col 0) which is always
// a zeroed pad word: rows<=32 -> next row's left pad; plane0 row33 -> plane1
// row0 col0; plane1 row33 -> the explicit zeroed TAIL float4 below.
#define SMSZ    (2*PLANE + 4)

// 16B async copy global->shared (LDGSTS.128)
__device__ __forceinline__ void cp16(float* dst_smem, const float* src) {
    uint32_t d = (uint32_t)__cvta_generic_to_shared(dst_smem);
    asm volatile("cp.async.cg.shared.global [%0], [%1], 16;\n" :: "r"(d), "l"(src));
}

// gate(a,b) = c0 + ca*a + cb*b + cab*a*b, factored to 3 FMAs
__device__ __forceinline__ float gate3(const float4 k, float a, float b) {
    return fmaf(fmaf(k.w, b, k.y), a, fmaf(k.z, b, k.x));
}

// ---------------------------------------------------------------------------
// 128-thread block per (batch, oc); grid 2048. 32 regs x 128 thr x 16 blocks
// = one SM's regfile -> 16 blocks/SM cap -> whole grid in ONE wave (~14
// blocks, ~55 warps per SM). Small blocks de-phase memory bursts; the single
// barrier covers only 4 warps. PW=36 layout (R14) + 1 zeroed tail float4
// makes every leaf read exactly correct. Hot loop: 8 LDS + 21 FMA + 1 STG
// per pixel, 8 px/thread, all offsets compile-time.
// ---------------------------------------------------------------------------
__global__ void __launch_bounds__(128, 16)
tree_kernel(const float* __restrict__ x,
            const float* __restrict__ w,
            const int*   __restrict__ leaf_idx,
            float*       __restrict__ out)
{
    __shared__ __align__(16) float  sm[SMSZ];        // 9808 B
    __shared__ __align__(16) float  s_coef[16];
    __shared__ int s_off[8];

    const int blk = blockIdx.x;          // 0..2047
    const int oc  = blk & (C_OUT - 1);
    const int b   = blk >> 7;
    const int tid = threadIdx.x;         // 0..127

    // --- channels (broadcast LDG; const-div -> mul-hi) ---------------------
    const int chA = __ldg(&leaf_idx[oc * 8 + 0]) / 9;
    const int chB = __ldg(&leaf_idx[oc * 8 + 4]) / 9;

    // --- leaf offsets: threads 0..7 ----------------------------------------
    if (tid < 8) {
        int idx = __ldg(&leaf_idx[oc * 8 + tid]);
        int ch  = idx / 9;
        int pos = idx - ch * 9;
        int ki  = pos / 3;
        int kj  = pos - ki * 3;
        s_off[tid] = (tid >> 2) * PLANE + ki * PW + kj + 3;
    }

    // --- softmax -> 4 affine coefficients, threads 0..3 (gate = tid) -------
    // op order: 0, ab, a-ab, a, b-ab, b, s-2ab, s-ab, 1-(s-ab), 1-(s-2ab),
    //           1-b, 1-b+ab, 1-a, 1-a+ab, 1-ab, 1
    if (tid < 4) {
        const float T0[16]  = {0,0,0,0,0,0,0,0, 1, 1, 1, 1, 1, 1, 1, 1};
        const float TA[16]  = {0,0,1,1,0,0,1,1,-1,-1, 0, 0,-1,-1, 0, 0};
        const float TB[16]  = {0,0,0,0,1,1,1,1,-1,-1,-1,-1, 0, 0, 0, 0};
        const float TAB[16] = {0,1,-1,0,-1,0,-2,-1, 1, 2, 0, 1, 0, 1,-1, 0};

        const float* wp = w + (oc * 7 + tid) * 16;   // weights [C_out, 7, 16]

        float m = wp[0];
        #pragma unroll
        for (int i = 1; i < 16; i++) m = fmaxf(m, wp[i]);

        float e[16];
        float s = 0.f;
        #pragma unroll
        for (int i = 0; i < 16; i++) { e[i] = __expf(wp[i] - m); s += e[i]; }
        float inv = 1.f / s;

        float c0 = 0.f, ca = 0.f, cb = 0.f, cab = 0.f;
        #pragma unroll
        for (int i = 0; i < 16; i++) {
            c0  += e[i] * T0[i];
            ca  += e[i] * TA[i];
            cb  += e[i] * TB[i];
            cab += e[i] * TAB[i];
        }
        s_coef[tid * 4 + 0] = c0 * inv;
        s_coef[tid * 4 + 1] = ca * inv;
        s_coef[tid * 4 + 2] = cb * inv;
        s_coef[tid * 4 + 3] = cab * inv;
    }

    // --- zero borders: 50 float4 per plane + 1 tail float4 (101 tasks) -----
    // k<32: rows 1..32 col-group 0; 32..40: row 0 groups 0..8;
    // 41..49: row 33 groups 0..8. Thread 100 zeroes the tail.
    {
        float4 z = make_float4(0.f, 0.f, 0.f, 0.f);
        if (tid < 100) {
            int p = tid >= 50;
            int k = tid - (p ? 50 : 0);
            int f4;
            if (k < 32)      f4 = (k + 1) * (PW / 4);      // rows 1..32, cols 0-3
            else if (k < 41) f4 = (k - 32);                // row 0, groups 0..8
            else             f4 = 33 * (PW / 4) + (k - 41);// row 33, groups 0..8
            ((float4*)sm)[p * PLANE4 + f4] = z;
        } else if (tid == 100) {
            ((float4*)sm)[2 * PLANE4] = z;                 // tail: sm[2448..2451]
        }
    }

    // --- stage: 2 planes x 32 rows x 8 chunks = 512 cp16 (4 per thread) ----
    {
        const float* xb = x + ((size_t)b * C_IN) * (HH * WW);
        #pragma unroll
        for (int i = 0; i < 4; i++) {
            int t  = tid + i * 128;      // 0..511
            int p  = t >> 8;
            int j  = t & 255;            // r*8 + c4
            int r  = j >> 3;
            int c4 = j & 7;
            const float* src = xb + ((p ? chB : chA) << 10) + j * 4;
            cp16(sm + p * PLANE + (r + 1) * PW + 4 + c4 * 4, src);
        }
        asm volatile("cp.async.commit_group;\n");
    }

    asm volatile("cp.async.wait_group 0;\n");
    __syncthreads();                     // 4 warps only

    // Coefficients to registers (4x LDS.128)
    const float4* cf = (const float4*)s_coef;
    const float4 k0 = cf[0], k1 = cf[1], k2 = cf[2], k3 = cf[3];

    // Per-thread base pixel: y0 = tid>>5 (0..3), x = tid&31; rows y0+4t
    const int pb0 = (tid >> 5) * PW + (tid & 31);
    const int o0 = s_off[0] + pb0, o1 = s_off[1] + pb0;
    const int o2 = s_off[2] + pb0, o3 = s_off[3] + pb0;
    const int o4 = s_off[4] + pb0, o5 = s_off[5] + pb0;
    const int o6 = s_off[6] + pb0, o7 = s_off[7] + pb0;

    float* ob = out + (size_t)blk * (HH * WW) + tid;

    #pragma unroll
    for (int t = 0; t < 8; t++) {
        const int d = t * 4 * PW;        // +4 rows per step (128 pixels)

        float l0 = sm[o0 + d], l1 = sm[o1 + d];
        float l2 = sm[o2 + d], l3 = sm[o3 + d];
        float l4 = sm[o4 + d], l5 = sm[o5 + d];
        float l6 = sm[o6 + d], l7 = sm[o7 + d];

        // level 0: weight rows 0,1,2,3
        float m0 = gate3(k0, l0, l1);
        float m1 = gate3(k1, l2, l3);
        float m2 = gate3(k2, l4, l5);
        float m3 = gate3(k3, l6, l7);
        // level 1: rows 1,2
        float n0 = gate3(k1, m0, m1);
        float n1 = gate3(k2, m2, m3);
        // level 2: row 3
        float r  = gate3(k3, n0, n1);

        ob[t * 128] = r;
    }
}

extern "C" void kernel_launch(void* const* d_in, const int* in_sizes, int n_in,
                              void* d_out, int out_size)
{
    const float* x   = (const float*)d_in[0];          // [16,64,32,32]
    const float* w   = (const float*)d_in[1];          // [128,7,16]
    const int*   idx = (const int*)d_in[2];            // [128,8]
    float*       out = (float*)d_out;                  // [16,128,32,32]

    tree_kernel<<<BATCH * C_OUT, 128>>>(x, w, idx, out);
}